// round 2
// baseline (speedup 1.0000x reference)
#include <cuda_runtime.h>
#include <math.h>
#include <stdint.h>

#define DIMV 128

static const long V  = 50000;
static const long C  = 150000;
static const long EP = 200000;
static const long EN = 200000;
static const int  NITER = 4;

// ---------------- scratch layout (floats) ----------------
#define O_MSG_PV2C 0L
#define O_MSG_NV2C (O_MSG_PV2C + V*DIMV)
#define O_MSG_PC2V (O_MSG_NV2C + V*DIMV)
#define O_MSG_NC2V (O_MSG_PC2V + C*DIMV)
#define O_HID      (O_MSG_NC2V + C*DIMV)
#define O_AGG_PC   (O_HID + C*DIMV)
#define O_AGG_NC   (O_AGG_PC + C*DIMV)
#define O_AGG_PV   (O_AGG_NC + C*DIMV)
#define O_AGG_NV   (O_AGG_PV + V*DIMV)
#define O_DEG_PV   (O_AGG_NV + V*DIMV)
#define O_DEG_NV   (O_DEG_PV + V)
#define O_DEG_PC   (O_DEG_NV + V)
#define O_DEG_NC   (O_DEG_PC + C)
#define O_PNORM    (O_DEG_NC + C)
#define O_NNORM    (O_PNORM + EP)
#define O_IDX      (O_NNORM + EN)
#define SCRATCH_TOTAL (O_IDX + 2*EP + 2*EN)

__device__ float g_scratch[SCRATCH_TOTAL];

// ---------------- small kernels ----------------

// per-edge endpoint gather + degree accumulation
__global__ void deg_kernel(const int* __restrict__ ev, const int* __restrict__ ec,
                           const int* __restrict__ sel, int nE,
                           float* __restrict__ degv, float* __restrict__ degc,
                           int* __restrict__ outv, int* __restrict__ outc)
{
    int e = blockIdx.x * blockDim.x + threadIdx.x;
    if (e >= nE) return;
    int ed = sel[e];
    int v = ev[ed], c = ec[ed];
    outv[e] = v; outc[e] = c;
    atomicAdd(&degv[v], 1.0f);
    atomicAdd(&degc[c], 1.0f);
}

__global__ void norm_kernel(const int* __restrict__ iv, const int* __restrict__ ic,
                            const float* __restrict__ degv, const float* __restrict__ degc,
                            float* __restrict__ ninv, int nE)
{
    int e = blockIdx.x * blockDim.x + threadIdx.x;
    if (e >= nE) return;
    float dv = fmaxf(degv[iv[e]], 1.0f);
    float dc = fmaxf(degc[ic[e]], 1.0f);
    ninv[e] = 1.0f / (sqrtf(dv) * sqrtf(dc));
}

__device__ __forceinline__ void red_add_v4(float* addr, float4 v)
{
    asm volatile("red.global.add.v4.f32 [%0], {%1,%2,%3,%4};"
                 :: "l"(addr), "f"(v.x), "f"(v.y), "f"(v.z), "f"(v.w) : "memory");
}

// one warp per edge: gather msg rows for both directions, scale by 1/norm,
// vector-reduce into destination aggregates.
__global__ void scatter_kernel(const int* __restrict__ si, const int* __restrict__ di,
                               const float* __restrict__ msgS, const float* __restrict__ msgD,
                               const float* __restrict__ ninv,
                               float* __restrict__ aggD, float* __restrict__ aggS, int nE)
{
    int w = (blockIdx.x * blockDim.x + threadIdx.x) >> 5;
    int lane = threadIdx.x & 31;
    if (w >= nE) return;
    int s = si[w];
    int d = di[w];
    float nv = ninv[w];
    float4 a = ((const float4*)(msgS + (long)s * DIMV))[lane];
    float4 b = ((const float4*)(msgD + (long)d * DIMV))[lane];
    a.x *= nv; a.y *= nv; a.z *= nv; a.w *= nv;
    b.x *= nv; b.y *= nv; b.z *= nv; b.w *= nv;
    red_add_v4(aggD + (long)d * DIMV + lane * 4, a);
    red_add_v4(aggS + (long)s * DIMV + lane * 4, b);
}

// ---------------- GEMM: out[N,128] = X[N,128] @ W[128,128] (+bias)(relu)(accum) ----------------
// MODE 0: relu(X@W + bias)    MODE 1: X@W + bias    MODE 2: out += X@W
template<int MODE>
__global__ __launch_bounds__(256)
void gemm128_kernel(const float* __restrict__ X, const float* __restrict__ W,
                    const float* __restrict__ bias, float* __restrict__ out, int N)
{
    extern __shared__ float sm[];
    float4* Ws = (float4*)sm;             // 128x128 = 4096 float4
    float4* As = (float4*)(sm + 16384);   // 64x128  = 2048 float4
    const int tid = threadIdx.x;
    const long row0 = (long)blockIdx.x * 64;

    const float4* Wg = (const float4*)W;
    #pragma unroll
    for (int i = 0; i < 16; i++) Ws[tid + i * 256] = Wg[tid + i * 256];

    #pragma unroll
    for (int i = 0; i < 8; i++) {
        int idx = tid + i * 256;
        int r = idx >> 5, c4 = idx & 31;
        float4 v = make_float4(0.f, 0.f, 0.f, 0.f);
        long rr = row0 + r;
        if (rr < N) v = ((const float4*)X)[rr * 32 + c4];
        As[idx] = v;
    }
    __syncthreads();

    const int cg = tid & 31;   // cols cg*4 .. cg*4+3
    const int rg = tid >> 5;   // rows rg*8 .. rg*8+7

    float4 bv = make_float4(0.f, 0.f, 0.f, 0.f);
    if (MODE != 2) bv = ((const float4*)bias)[cg];
    float acc[8][4];
    #pragma unroll
    for (int i = 0; i < 8; i++) {
        acc[i][0] = bv.x; acc[i][1] = bv.y; acc[i][2] = bv.z; acc[i][3] = bv.w;
    }

    #pragma unroll 4
    for (int k4 = 0; k4 < 32; k4++) {
        float4 w0 = Ws[(k4 * 4 + 0) * 32 + cg];
        float4 w1 = Ws[(k4 * 4 + 1) * 32 + cg];
        float4 w2 = Ws[(k4 * 4 + 2) * 32 + cg];
        float4 w3 = Ws[(k4 * 4 + 3) * 32 + cg];
        #pragma unroll
        for (int i = 0; i < 8; i++) {
            float4 a = As[(rg * 8 + i) * 32 + k4];
            acc[i][0] = fmaf(a.x, w0.x, acc[i][0]);
            acc[i][0] = fmaf(a.y, w1.x, acc[i][0]);
            acc[i][0] = fmaf(a.z, w2.x, acc[i][0]);
            acc[i][0] = fmaf(a.w, w3.x, acc[i][0]);
            acc[i][1] = fmaf(a.x, w0.y, acc[i][1]);
            acc[i][1] = fmaf(a.y, w1.y, acc[i][1]);
            acc[i][1] = fmaf(a.z, w2.y, acc[i][1]);
            acc[i][1] = fmaf(a.w, w3.y, acc[i][1]);
            acc[i][2] = fmaf(a.x, w0.z, acc[i][2]);
            acc[i][2] = fmaf(a.y, w1.z, acc[i][2]);
            acc[i][2] = fmaf(a.z, w2.z, acc[i][2]);
            acc[i][2] = fmaf(a.w, w3.z, acc[i][2]);
            acc[i][3] = fmaf(a.x, w0.w, acc[i][3]);
            acc[i][3] = fmaf(a.y, w1.w, acc[i][3]);
            acc[i][3] = fmaf(a.z, w2.w, acc[i][3]);
            acc[i][3] = fmaf(a.w, w3.w, acc[i][3]);
        }
    }

    #pragma unroll
    for (int i = 0; i < 8; i++) {
        long r = row0 + rg * 8 + i;
        if (r >= N) break;
        float4 o = make_float4(acc[i][0], acc[i][1], acc[i][2], acc[i][3]);
        if (MODE == 0) {
            o.x = fmaxf(o.x, 0.f); o.y = fmaxf(o.y, 0.f);
            o.z = fmaxf(o.z, 0.f); o.w = fmaxf(o.w, 0.f);
        }
        float4* op = (float4*)(out + r * DIMV) + cg;
        if (MODE == 2) {
            float4 p = *op;
            o.x += p.x; o.y += p.y; o.z += p.z; o.w += p.w;
        }
        *op = o;
    }
}

// ---------------- host side ----------------
#define GEMM_SMEM 98304

static void gemm(int mode, const float* X, const float* W, const float* bias,
                 float* out, long N)
{
    dim3 grid((unsigned)((N + 63) / 64));
    if (mode == 0)      gemm128_kernel<0><<<grid, 256, GEMM_SMEM>>>(X, W, bias, out, (int)N);
    else if (mode == 1) gemm128_kernel<1><<<grid, 256, GEMM_SMEM>>>(X, W, bias, out, (int)N);
    else                gemm128_kernel<2><<<grid, 256, GEMM_SMEM>>>(X, W, bias, out, (int)N);
}

extern "C" void kernel_launch(void* const* d_in, const int* in_sizes, int n_in,
                              void* d_out, int out_size)
{
    // Robust to whether the two leading int scalars (v_size, c_size) are
    // materialized as inputs: index the 14 real tensors from the end.
    const int ofs = n_in - 14;
    const int*   v_edge = (const int*)d_in[ofs + 0];
    const int*   c_edge = (const int*)d_in[ofs + 1];
    const int*   p_sel  = (const int*)d_in[ofs + 2];
    const int*   n_sel  = (const int*)d_in[ofs + 3];
    const float* v_emb0 = (const float*)d_in[ofs + 4];
    const float* c_emb0 = (const float*)d_in[ofs + 5];
    const float* W1     = (const float*)d_in[ofs + 6];
    const float* b1     = (const float*)d_in[ofs + 7];
    const float* W2     = (const float*)d_in[ofs + 8];
    const float* b2     = (const float*)d_in[ofs + 9];
    const float* cW     = (const float*)d_in[ofs + 10];
    const float* cB     = (const float*)d_in[ofs + 11];
    const float* vW     = (const float*)d_in[ofs + 12];
    const float* vB     = (const float*)d_in[ofs + 13];

    float* base = nullptr;
    cudaGetSymbolAddress((void**)&base, g_scratch);

    float* msgPV2C = base + O_MSG_PV2C;
    float* msgNV2C = base + O_MSG_NV2C;
    float* msgPC2V = base + O_MSG_PC2V;
    float* msgNC2V = base + O_MSG_NC2V;
    float* hid     = base + O_HID;
    float* aggPC   = base + O_AGG_PC;
    float* aggNC   = base + O_AGG_NC;
    float* aggPV   = base + O_AGG_PV;
    float* aggNV   = base + O_AGG_NV;
    float* degPV   = base + O_DEG_PV;
    float* degPC   = base + O_DEG_PC;
    float* degNV   = base + O_DEG_NV;
    float* degNC   = base + O_DEG_NC;
    float* pnorm   = base + O_PNORM;
    float* nnorm   = base + O_NNORM;
    int*   pv      = (int*)(base + O_IDX);
    int*   pc      = pv + EP;
    int*   nv      = pc + EP;
    int*   nc      = nv + EN;

    float* out = (float*)d_out;
    float* OV = out;                    // [5][V][128]
    float* OC = out + 5L * V * DIMV;    // [5][C][128]

    cudaFuncSetAttribute(gemm128_kernel<0>, cudaFuncAttributeMaxDynamicSharedMemorySize, GEMM_SMEM);
    cudaFuncSetAttribute(gemm128_kernel<1>, cudaFuncAttributeMaxDynamicSharedMemorySize, GEMM_SMEM);
    cudaFuncSetAttribute(gemm128_kernel<2>, cudaFuncAttributeMaxDynamicSharedMemorySize, GEMM_SMEM);

    // degrees + norms (iteration-invariant)
    cudaMemsetAsync(base + O_DEG_PV, 0, (2 * V + 2 * C) * sizeof(float));
    deg_kernel<<<(unsigned)((EP + 255) / 256), 256>>>(v_edge, c_edge, p_sel, (int)EP, degPV, degPC, pv, pc);
    deg_kernel<<<(unsigned)((EN + 255) / 256), 256>>>(v_edge, c_edge, n_sel, (int)EN, degNV, degNC, nv, nc);
    norm_kernel<<<(unsigned)((EP + 255) / 256), 256>>>(pv, pc, degPV, degPC, pnorm, (int)EP);
    norm_kernel<<<(unsigned)((EN + 255) / 256), 256>>>(nv, nc, degNV, degNC, nnorm, (int)EN);

    // iteration 0 embeddings straight into the output stacks
    cudaMemcpyAsync(OV, v_emb0, V * DIMV * sizeof(float), cudaMemcpyDeviceToDevice);
    cudaMemcpyAsync(OC, c_emb0, C * DIMV * sizeof(float), cudaMemcpyDeviceToDevice);

    for (int it = 0; it < NITER; it++) {
        const float* Vc = OV + (long)it * V * DIMV;
        const float* Cc = OC + (long)it * C * DIMV;
        float* Vn = OV + (long)(it + 1) * V * DIMV;
        float* Cn = OC + (long)(it + 1) * C * DIMV;

        // 4 message MLPs on node features (old embeddings)
        gemm(0, Vc, W1 + 0 * 16384, b1 + 0 * 128, hid, V);
        gemm(1, hid, W2 + 0 * 16384, b2 + 0 * 128, msgPV2C, V);
        gemm(0, Vc, W1 + 1 * 16384, b1 + 1 * 128, hid, V);
        gemm(1, hid, W2 + 1 * 16384, b2 + 1 * 128, msgNV2C, V);
        gemm(0, Cc, W1 + 2 * 16384, b1 + 2 * 128, hid, C);
        gemm(1, hid, W2 + 2 * 16384, b2 + 2 * 128, msgPC2V, C);
        gemm(0, Cc, W1 + 3 * 16384, b1 + 3 * 128, hid, C);
        gemm(1, hid, W2 + 3 * 16384, b2 + 3 * 128, msgNC2V, C);

        // zero the (contiguous) aggregate buffers, then scatter both edge sets
        cudaMemsetAsync(aggPC, 0, (2 * C + 2 * V) * DIMV * sizeof(float));
        scatter_kernel<<<(unsigned)(EP / 8), 256>>>(pv, pc, msgPV2C, msgPC2V, pnorm, aggPC, aggPV, (int)EP);
        scatter_kernel<<<(unsigned)(EN / 8), 256>>>(nv, nc, msgNV2C, msgNC2V, nnorm, aggNC, aggNV, (int)EN);

        // clause update: concat(Cc, aggPC, aggNC) @ cW + cB   (3 chained K=128 passes)
        gemm(1, Cc,    cW + 0 * 16384, cB, Cn, C);
        gemm(2, aggPC, cW + 1 * 16384, nullptr, Cn, C);
        gemm(2, aggNC, cW + 2 * 16384, nullptr, Cn, C);

        // variable update
        gemm(1, Vc,    vW + 0 * 16384, vB, Vn, V);
        gemm(2, aggPV, vW + 1 * 16384, nullptr, Vn, V);
        gemm(2, aggNV, vW + 2 * 16384, nullptr, Vn, V);
    }
}